// round 10
// baseline (speedup 1.0000x reference)
#include <cuda_runtime.h>
#include <cstdint>

// ---------------- problem constants ----------------
#define B_DIM 128
#define H_DIM 101            // 100 hidden + leading 1
#define AV 10201             // 101*101
#define F_DIM 1030301        // 101^3
#define P_DIM 300
#define KT 32                // K per pipeline tile
#define TILES 32197          // ceil(F_DIM / 32), last tile has 29 valid k
#define NCTA 148
#define NTHR 256
#define A_BYTES (128 * KT * 4)        // 16384
#define B_BYTES (320 * KT * 4)        // 40960 (rows 300..319 garbage-tolerated)
#define STG_BYTES (A_BYTES + B_BYTES) // 57344
#define DYN_SMEM (3 * STG_BYTES)      // 172032
#define RPARTS 8

// ---------------- device scratch (no allocs allowed) ----------------
__device__ float g_HA[B_DIM * H_DIM];
__device__ float g_HV[B_DIM * H_DIM];
__device__ float g_HT[B_DIM * H_DIM];
__device__ float g_VT[B_DIM * AV];                               // 5.2 MB, L2-resident
__device__ __align__(16) float g_part[(size_t)NCTA * B_DIM * P_DIM];  // split-K partials
__device__ __align__(16) float g_R4[RPARTS * B_DIM * P_DIM];     // phase-1 reduction
__device__ __align__(16) float g_H[B_DIM * P_DIM];               // relu(fusion@W1^T + b1)

// ---------------- helpers ----------------
__device__ __forceinline__ uint32_t smem_u32(const void* p) {
    uint32_t a;
    asm("{ .reg .u64 t; cvta.to.shared.u64 t, %1; cvt.u32.u64 %0, t; }" : "=r"(a) : "l"(p));
    return a;
}
__device__ __forceinline__ uint32_t f2tf(float x) {   // round-to-nearest tf32
    uint32_t r; asm("cvt.rna.tf32.f32 %0, %1;" : "=r"(r) : "f"(x)); return r;
}
__device__ __forceinline__ void sts128(uint32_t a, uint32_t v0, uint32_t v1,
                                       uint32_t v2, uint32_t v3) {
    asm volatile("st.shared.v4.b32 [%0], {%1,%2,%3,%4};"
                 :: "r"(a), "r"(v0), "r"(v1), "r"(v2), "r"(v3) : "memory");
}
__device__ __forceinline__ void lds128(uint32_t a, uint32_t& v0, uint32_t& v1,
                                       uint32_t& v2, uint32_t& v3) {
    asm volatile("ld.shared.v4.b32 {%0,%1,%2,%3}, [%4];"
                 : "=r"(v0), "=r"(v1), "=r"(v2), "=r"(v3) : "r"(a));
}
__device__ __forceinline__ void cpasync4(uint32_t dst, const float* src) {
    asm volatile("cp.async.ca.shared.global [%0], [%1], 4;" :: "r"(dst), "l"(src) : "memory");
}
__device__ __forceinline__ void cp_commit() {
    asm volatile("cp.async.commit_group;" ::: "memory");
}
__device__ __forceinline__ void cp_wait1() {
    asm volatile("cp.async.wait_group 1;" ::: "memory");
}
__device__ __forceinline__ void mma_tf32(float& d0, float& d1, float& d2, float& d3,
                                         uint32_t a0, uint32_t a1, uint32_t a2, uint32_t a3,
                                         uint32_t b0, uint32_t b1) {
    asm volatile("mma.sync.aligned.m16n8k8.row.col.f32.tf32.tf32.f32 "
                 "{%0,%1,%2,%3}, {%4,%5,%6,%7}, {%8,%9}, {%0,%1,%2,%3};"
                 : "+f"(d0), "+f"(d1), "+f"(d2), "+f"(d3)
                 : "r"(a0), "r"(a1), "r"(a2), "r"(a3), "r"(b0), "r"(b1));
}

// ---------------- kernel 1: three small encoders ----------------
__global__ void enc_kernel(const float* __restrict__ ax, const float* __restrict__ vx,
                           const float* __restrict__ tx,
                           const float* __restrict__ Wa, const float* __restrict__ ba,
                           const float* __restrict__ Wv, const float* __restrict__ bv,
                           const float* __restrict__ Wt, const float* __restrict__ bt) {
    __shared__ float xs[300];
    int b = blockIdx.x, m = blockIdx.y;
    const float* x    = (m == 0) ? ax : (m == 1) ? vx : tx;
    const float* W    = (m == 0) ? Wa : (m == 1) ? Wv : Wt;
    const float* bias = (m == 0) ? ba : (m == 1) ? bv : bt;
    float* H          = (m == 0) ? g_HA : (m == 1) ? g_HV : g_HT;
    for (int i = threadIdx.x; i < 300; i += blockDim.x) xs[i] = x[b * 300 + i];
    __syncthreads();
    int j = threadIdx.x;
    if (j == 0) H[b * H_DIM] = 1.0f;
    if (j < 100) {
        const float* w = W + j * 300;
        float s = 0.0f;
        #pragma unroll 4
        for (int p = 0; p < 300; p++) s += xs[p] * __ldg(w + p);
        H[b * H_DIM + 1 + j] = s + __ldg(bias + j);
    }
}

// ---------------- kernel 2: VT[b, v*101+t] = _v[b,v] * _t[b,t] ----------------
__global__ void vt_kernel() {
    __shared__ float hv[H_DIM], ht[H_DIM];
    int b = blockIdx.x;
    if (threadIdx.x < H_DIM) {
        hv[threadIdx.x] = g_HV[b * H_DIM + threadIdx.x];
        ht[threadIdx.x] = g_HT[b * H_DIM + threadIdx.x];
    }
    __syncthreads();
    for (int i = threadIdx.x; i < AV; i += 256) {
        int v = i / 101, t = i - v * 101;
        g_VT[b * AV + i] = hv[v] * ht[t];
    }
}

// ---------------- kernel 3: main split-K mma.sync GEMM ----------------
// 8 warps, warp grid 2M x 4N (warp tile 64 x 80). KT=32.
// SMEM per stage: A[128 rows][32 words], B[320 rows][32 words], k contiguous,
// 16B chunks XOR-swizzled: chunk' = chunk ^ ((row & 1) * 4).
// Identical MMA-slot <-> physical-k bijection for A and B makes contiguous-k legal.
__global__ void __launch_bounds__(NTHR, 1) main_kernel(const float* __restrict__ W1) {
    extern __shared__ char dyn[];
    uint32_t base_s = smem_u32(dyn);

    int tid = threadIdx.x, wid = tid >> 5, lane = tid & 31;
    int cta = blockIdx.x;
    int wm = wid & 1;          // M half: rows wm*64
    int wn = wid >> 1;         // N block: cols wn*80
    int lr = lane >> 2;        // 0..7
    int lc = lane & 3;         // 0..3
    uint32_t swlo = (uint32_t)(lr & 1) * 4;   // consumer swizzle (row parity == lr parity)

    // contiguous K-tile range for this CTA
    int q = TILES / NCTA;                  // 217
    int r = TILES - q * NCTA;              // 81
    int t0 = cta * q + min(cta, r);
    int nt = q + (cta < r ? 1 : 0);

    // ---- producer state (rolling, advanced once per produced tile) ----
    int kp = t0 * KT;                      // k0 of produce cursor
    int ap = kp / AV;
    int vp = kp - ap * AV;

    // A producer mapping
    int prow0 = wid * 8 + (lane >> 2);
    int pc0   = lane & 3;
    // B producer mapping: warp w loads row n = w + 8i, 128B per row per tile
    int bn0 = tid >> 5;
    int bw0 = tid & 31;
    const float* Wrow = W1 + (size_t)bn0 * F_DIM;
    uint32_t bdst0 = (uint32_t)(bn0 * 128 + (((bw0 >> 2) ^ ((bn0 & 1) * 4)) * 16) + (bw0 & 3) * 4);

    float acc[4][10][4];
    #pragma unroll
    for (int m = 0; m < 4; m++)
        #pragma unroll
        for (int n = 0; n < 10; n++)
            #pragma unroll
            for (int e = 0; e < 4; e++) acc[m][n][e] = 0.0f;

#define PRODUCE(S) do {                                                               \
    uint32_t aB = base_s + (S) * STG_BYTES;                                           \
    uint32_t bB = aB + A_BYTES;                                                       \
    /* ---- A tile ---- */                                                            \
    if (vp <= AV - KT && kp + KT <= F_DIM) {  /* fast: 'a' constant over tile */      \
        _Pragma("unroll")                                                             \
        for (int it = 0; it < 2; it++) {                                              \
            int row = it * 64 + prow0;                                                \
            float ha = g_HA[row * H_DIM + ap];                                        \
            const float* vrow = g_VT + (size_t)row * AV + vp;                         \
            uint32_t abase = aB + row * 128;                                          \
            uint32_t rsw = (uint32_t)(row & 1) * 4;                                   \
            _Pragma("unroll")                                                         \
            for (int j = 0; j < 2; j++) {                                             \
                int c = pc0 + 4 * j;                                                  \
                uint32_t v0 = f2tf(ha * vrow[4 * c + 0]);                             \
                uint32_t v1 = f2tf(ha * vrow[4 * c + 1]);                             \
                uint32_t v2 = f2tf(ha * vrow[4 * c + 2]);                             \
                uint32_t v3 = f2tf(ha * vrow[4 * c + 3]);                             \
                sts128(abase + (((uint32_t)c ^ rsw) * 16), v0, v1, v2, v3);           \
            }                                                                         \
        }                                                                             \
    } else {                                  /* slow: per-element, division-free */  \
        _Pragma("unroll")                                                             \
        for (int it = 0; it < 2; it++) {                                              \
            int row = it * 64 + prow0;                                                \
            uint32_t abase = aB + row * 128;                                          \
            uint32_t rsw = (uint32_t)(row & 1) * 4;                                   \
            _Pragma("unroll")                                                         \
            for (int j = 0; j < 2; j++) {                                             \
                int c = pc0 + 4 * j;                                                  \
                uint32_t v[4];                                                        \
                _Pragma("unroll")                                                     \
                for (int e = 0; e < 4; e++) {                                         \
                    int off = 4 * c + e;                                              \
                    int k = kp + off;                                                 \
                    float val = 0.0f;                                                 \
                    if (k < F_DIM) {                                                  \
                        int vv = vp + off;                                            \
                        int wrap = (vv >= AV);                                        \
                        int a = ap + wrap;                                            \
                        int vt = vv - (wrap ? AV : 0);                                \
                        val = g_HA[row * H_DIM + a] * g_VT[(size_t)row * AV + vt];    \
                    }                                                                 \
                    v[e] = f2tf(val);                                                 \
                }                                                                     \
                sts128(abase + (((uint32_t)c ^ rsw) * 16), v[0], v[1], v[2], v[3]);   \
            }                                                                         \
        }                                                                             \
    }                                                                                 \
    /* ---- B tile: 300 rows x 32 words, rolling pointers ---- */                     \
    {                                                                                 \
        int kk = kp + bw0;                                                            \
        const float* src = Wrow + ((kk < F_DIM) ? kk : 0);  /* clamp: A zeros cover */\
        uint32_t dst = bB + bdst0;                                                    \
        _Pragma("unroll")                                                             \
        for (int i = 0; i < 37; i++) {                                                \
            cpasync4(dst, src);                                                       \
            dst += 8 * 128;                                                           \
            src += (size_t)8 * F_DIM;                                                 \
        }                                                                             \
        if (tid < 128) cpasync4(dst, src);  /* rows 296..299 */                       \
    }                                                                                 \
    kp += KT; vp += KT; if (vp >= AV) { vp -= AV; ap++; }                             \
} while (0)

    // prologue: produce stages 0,1
    PRODUCE(0); cp_commit();
    PRODUCE(1); cp_commit();

    uint32_t aoff = (uint32_t)((wm * 64 + lr) * 128);
    uint32_t boff = (uint32_t)((wn * 80 + lr) * 128);

    int stage_c = 0, stage_p = 2;
    for (int c = 0; c < nt; c++) {
        cp_wait1();
        __syncthreads();
        if (c + 2 < nt) PRODUCE(stage_p);
        cp_commit();

        uint32_t aB = base_s + stage_c * STG_BYTES;
        uint32_t bB = aB + A_BYTES;

        #pragma unroll
        for (int g = 0; g < 2; g++) {
            uint32_t chc = (((uint32_t)(4 * g + lc)) ^ swlo) * 16;
            // A fragments for this k-half: 8 lds128 = 32 regs, loaded once
            uint32_t A[8][4];
            {
                uint32_t aaddr = aB + aoff + chc;
                #pragma unroll
                for (int m = 0; m < 4; m++) {
                    lds128(aaddr,            A[2*m  ][0], A[2*m  ][1], A[2*m  ][2], A[2*m  ][3]);
                    lds128(aaddr + 8 * 128,  A[2*m+1][0], A[2*m+1][1], A[2*m+1][2], A[2*m+1][3]);
                    aaddr += 16 * 128;
                }
            }
            // B fragments stream through a 2-deep rolling buffer (prefetch n+1)
            uint32_t baddr = bB + boff + chc;
            uint32_t bcur[4], bnxt[4];
            lds128(baddr, bcur[0], bcur[1], bcur[2], bcur[3]);
            #pragma unroll
            for (int n = 0; n < 10; n++) {
                if (n < 9) {
                    baddr += 8 * 128;
                    lds128(baddr, bnxt[0], bnxt[1], bnxt[2], bnxt[3]);
                }
                uint32_t t0r = f2tf(__uint_as_float(bcur[0]));
                uint32_t t1r = f2tf(__uint_as_float(bcur[1]));
                uint32_t t2r = f2tf(__uint_as_float(bcur[2]));
                uint32_t t3r = f2tf(__uint_as_float(bcur[3]));
                #pragma unroll
                for (int m = 0; m < 4; m++) {
                    mma_tf32(acc[m][n][0], acc[m][n][1], acc[m][n][2], acc[m][n][3],
                             A[2*m][0], A[2*m+1][0], A[2*m][1], A[2*m+1][1], t0r, t1r);
                    mma_tf32(acc[m][n][0], acc[m][n][1], acc[m][n][2], acc[m][n][3],
                             A[2*m][2], A[2*m+1][2], A[2*m][3], A[2*m+1][3], t2r, t3r);
                }
                #pragma unroll
                for (int e = 0; e < 4; e++) bcur[e] = bnxt[e];
            }
        }
        stage_c = (stage_c == 2) ? 0 : stage_c + 1;
        stage_p = (stage_p == 2) ? 0 : stage_p + 1;
    }

    // ---- epilogue: deterministic per-CTA partials ----
    float* dst = g_part + (size_t)cta * B_DIM * P_DIM;
    #pragma unroll
    for (int m = 0; m < 4; m++) {
        int row = wm * 64 + m * 16 + lr;
        #pragma unroll
        for (int n = 0; n < 10; n++) {
            int col = wn * 80 + n * 8 + lc * 2;
            if (col < 300) {
                float2 v0 = make_float2(acc[m][n][0], acc[m][n][1]);
                float2 v1 = make_float2(acc[m][n][2], acc[m][n][3]);
                *reinterpret_cast<float2*>(dst + (size_t)row * P_DIM + col) = v0;
                *reinterpret_cast<float2*>(dst + (size_t)(row + 8) * P_DIM + col) = v1;
            }
        }
    }
#undef PRODUCE
}

// ---------------- kernel 4a: split-K reduce phase 1 (148 -> 8) ----------------
__global__ void reduce1_kernel() {
    const int NG4 = B_DIM * P_DIM / 4;                    // 9600
    int g4 = blockIdx.x * blockDim.x + threadIdx.x;
    if (g4 >= NG4) return;
    int part = blockIdx.y;                                // 0..7
    int c0 = part * 18 + min(part, 4);                    // 148 = 4*19 + 4*18
    int cn = 18 + (part < 4 ? 1 : 0);
    const float4* base = reinterpret_cast<const float4*>(g_part) + (size_t)c0 * NG4 + g4;
    float4 s0 = make_float4(0.f, 0.f, 0.f, 0.f);
    float4 s1 = make_float4(0.f, 0.f, 0.f, 0.f);
    float4 s2 = make_float4(0.f, 0.f, 0.f, 0.f);
    float4 s3 = make_float4(0.f, 0.f, 0.f, 0.f);
    int c = 0;
    #pragma unroll
    for (; c + 4 <= 18; c += 4) {
        float4 v0 = base[(size_t)(c + 0) * NG4];
        float4 v1 = base[(size_t)(c + 1) * NG4];
        float4 v2 = base[(size_t)(c + 2) * NG4];
        float4 v3 = base[(size_t)(c + 3) * NG4];
        s0.x += v0.x; s0.y += v0.y; s0.z += v0.z; s0.w += v0.w;
        s1.x += v1.x; s1.y += v1.y; s1.z += v1.z; s1.w += v1.w;
        s2.x += v2.x; s2.y += v2.y; s2.z += v2.z; s2.w += v2.w;
        s3.x += v3.x; s3.y += v3.y; s3.z += v3.z; s3.w += v3.w;
    }
    for (; c < cn; c++) {
        float4 v0 = base[(size_t)c * NG4];
        s0.x += v0.x; s0.y += v0.y; s0.z += v0.z; s0.w += v0.w;
    }
    float4 o;
    o.x = (s0.x + s1.x) + (s2.x + s3.x);
    o.y = (s0.y + s1.y) + (s2.y + s3.y);
    o.z = (s0.z + s1.z) + (s2.z + s3.z);
    o.w = (s0.w + s1.w) + (s2.w + s3.w);
    reinterpret_cast<float4*>(g_R4)[part * NG4 + g4] = o;
}

// ---------------- kernel 4b: reduce phase 2 + bias + relu ----------------
__global__ void reduce2_kernel(const float* __restrict__ b1) {
    const int NG4 = B_DIM * P_DIM / 4;
    int g4 = blockIdx.x * blockDim.x + threadIdx.x;
    if (g4 >= NG4) return;
    const float4* R = reinterpret_cast<const float4*>(g_R4);
    float sx = 0.f, sy = 0.f, sz = 0.f, sw = 0.f;
    #pragma unroll
    for (int p = 0; p < RPARTS; p++) {
        float4 v = R[p * NG4 + g4];
        sx += v.x; sy += v.y; sz += v.z; sw += v.w;
    }
    int col = (g4 * 4) % P_DIM;
    float4 o;
    o.x = fmaxf(sx + __ldg(b1 + col + 0), 0.f);
    o.y = fmaxf(sy + __ldg(b1 + col + 1), 0.f);
    o.z = fmaxf(sz + __ldg(b1 + col + 2), 0.f);
    o.w = fmaxf(sw + __ldg(b1 + col + 3), 0.f);
    reinterpret_cast<float4*>(g_H)[g4] = o;
}

// ---------------- kernel 5: output layer ----------------
__global__ void out_kernel(const float* __restrict__ W2, const float* __restrict__ b2,
                           float* __restrict__ out) {
    __shared__ float w[P_DIM];
    int o = blockIdx.x;
    for (int i = threadIdx.x; i < P_DIM; i += blockDim.x) w[i] = W2[o * P_DIM + i];
    __syncthreads();
    int b = threadIdx.x;
    if (b < B_DIM) {
        const float* h = g_H + b * P_DIM;
        float s = __ldg(b2 + o);
        #pragma unroll 4
        for (int p = 0; p < P_DIM; p++) s += h[p] * w[p];
        out[b * P_DIM + o] = fmaxf(s, 0.0f);
    }
}

// ---------------- launch ----------------
extern "C" void kernel_launch(void* const* d_in, const int* in_sizes, int n_in,
                              void* d_out, int out_size) {
    const float* ax = (const float*)d_in[0];
    const float* vx = (const float*)d_in[1];
    const float* tx = (const float*)d_in[2];
    const float* Wa = (const float*)d_in[3];
    const float* ba = (const float*)d_in[4];
    const float* Wv = (const float*)d_in[5];
    const float* bv = (const float*)d_in[6];
    const float* Wt = (const float*)d_in[7];
    const float* bt = (const float*)d_in[8];
    const float* W1 = (const float*)d_in[9];
    const float* b1 = (const float*)d_in[10];
    const float* W2 = (const float*)d_in[11];
    const float* b2 = (const float*)d_in[12];
    float* out = (float*)d_out;

    cudaFuncSetAttribute(main_kernel, cudaFuncAttributeMaxDynamicSharedMemorySize, DYN_SMEM);

    enc_kernel<<<dim3(B_DIM, 3), 128>>>(ax, vx, tx, Wa, ba, Wv, bv, Wt, bt);
    vt_kernel<<<B_DIM, 256>>>();
    main_kernel<<<NCTA, NTHR, DYN_SMEM>>>(W1);
    reduce1_kernel<<<dim3((B_DIM * P_DIM / 4 + 255) / 256, RPARTS), 256>>>();
    reduce2_kernel<<<(B_DIM * P_DIM / 4 + 255) / 256, 256>>>(b1);
    out_kernel<<<P_DIM, 128>>>(W2, b2, out);
}

// round 11
// speedup vs baseline: 1.4095x; 1.4095x over previous
#include <cuda_runtime.h>
#include <cstdint>

// ---------------- problem constants ----------------
#define B_DIM 128
#define H_DIM 101            // 100 hidden + leading 1
#define AV 10201             // 101*101
#define F_DIM 1030301        // 101^3
#define P_DIM 300
#define KT 32                // K per pipeline tile
#define TILES 32197          // ceil(F_DIM / 32), last tile has 29 valid k
#define NCTA 148
#define NTHR 256
#define A_BYTES (128 * KT * 4)        // 16384
#define B_BYTES (320 * KT * 4)        // 40960 (rows 300..319 garbage-tolerated)
#define STG_BYTES (A_BYTES + B_BYTES) // 57344
#define DYN_SMEM (3 * STG_BYTES)      // 172032
#define RPARTS 8

// ---------------- device scratch (no allocs allowed) ----------------
__device__ float g_HA[B_DIM * H_DIM];
__device__ float g_HV[B_DIM * H_DIM];
__device__ float g_HT[B_DIM * H_DIM];
__device__ float g_VT[B_DIM * AV];                               // 5.2 MB, L2-resident
__device__ __align__(16) float g_part[(size_t)NCTA * B_DIM * P_DIM];  // split-K partials
__device__ __align__(16) float g_R4[RPARTS * B_DIM * P_DIM];     // phase-1 reduction
__device__ __align__(16) float g_H[B_DIM * P_DIM];               // relu(fusion@W1^T + b1)

// ---------------- helpers ----------------
__device__ __forceinline__ uint32_t smem_u32(const void* p) {
    uint32_t a;
    asm("{ .reg .u64 t; cvta.to.shared.u64 t, %1; cvt.u32.u64 %0, t; }" : "=r"(a) : "l"(p));
    return a;
}
// pack two fp32 -> f16x2 (hi goes to upper half, lo to lower half)
__device__ __forceinline__ uint32_t cvt2h(float hi, float lo) {
    uint32_t r;
    asm("cvt.rn.f16x2.f32 %0, %1, %2;" : "=r"(r) : "f"(hi), "f"(lo));
    return r;
}
__device__ __forceinline__ void sts128(uint32_t a, uint32_t v0, uint32_t v1,
                                       uint32_t v2, uint32_t v3) {
    asm volatile("st.shared.v4.b32 [%0], {%1,%2,%3,%4};"
                 :: "r"(a), "r"(v0), "r"(v1), "r"(v2), "r"(v3) : "memory");
}
__device__ __forceinline__ void lds128(uint32_t a, uint32_t& v0, uint32_t& v1,
                                       uint32_t& v2, uint32_t& v3) {
    asm volatile("ld.shared.v4.b32 {%0,%1,%2,%3}, [%4];"
                 : "=r"(v0), "=r"(v1), "=r"(v2), "=r"(v3) : "r"(a));
}
__device__ __forceinline__ void cpasync4(uint32_t dst, const float* src) {
    asm volatile("cp.async.ca.shared.global [%0], [%1], 4;" :: "r"(dst), "l"(src) : "memory");
}
__device__ __forceinline__ void cp_commit() {
    asm volatile("cp.async.commit_group;" ::: "memory");
}
__device__ __forceinline__ void cp_wait1() {
    asm volatile("cp.async.wait_group 1;" ::: "memory");
}
// fp16 MMA, m16n8k16, fp32 accumulate
__device__ __forceinline__ void mma_f16(float& d0, float& d1, float& d2, float& d3,
                                        uint32_t a0, uint32_t a1, uint32_t a2, uint32_t a3,
                                        uint32_t b0, uint32_t b1) {
    asm volatile("mma.sync.aligned.m16n8k16.row.col.f32.f16.f16.f32 "
                 "{%0,%1,%2,%3}, {%4,%5,%6,%7}, {%8,%9}, {%0,%1,%2,%3};"
                 : "+f"(d0), "+f"(d1), "+f"(d2), "+f"(d3)
                 : "r"(a0), "r"(a1), "r"(a2), "r"(a3), "r"(b0), "r"(b1));
}

// ---------------- kernel 1: three small encoders ----------------
__global__ void enc_kernel(const float* __restrict__ ax, const float* __restrict__ vx,
                           const float* __restrict__ tx,
                           const float* __restrict__ Wa, const float* __restrict__ ba,
                           const float* __restrict__ Wv, const float* __restrict__ bv,
                           const float* __restrict__ Wt, const float* __restrict__ bt) {
    __shared__ float xs[300];
    int b = blockIdx.x, m = blockIdx.y;
    const float* x    = (m == 0) ? ax : (m == 1) ? vx : tx;
    const float* W    = (m == 0) ? Wa : (m == 1) ? Wv : Wt;
    const float* bias = (m == 0) ? ba : (m == 1) ? bv : bt;
    float* H          = (m == 0) ? g_HA : (m == 1) ? g_HV : g_HT;
    for (int i = threadIdx.x; i < 300; i += blockDim.x) xs[i] = x[b * 300 + i];
    __syncthreads();
    int j = threadIdx.x;
    if (j == 0) H[b * H_DIM] = 1.0f;
    if (j < 100) {
        const float* w = W + j * 300;
        float s = 0.0f;
        #pragma unroll 4
        for (int p = 0; p < 300; p++) s += xs[p] * __ldg(w + p);
        H[b * H_DIM + 1 + j] = s + __ldg(bias + j);
    }
}

// ---------------- kernel 2: VT[b, v*101+t] = _v[b,v] * _t[b,t] ----------------
__global__ void vt_kernel() {
    __shared__ float hv[H_DIM], ht[H_DIM];
    int b = blockIdx.x;
    if (threadIdx.x < H_DIM) {
        hv[threadIdx.x] = g_HV[b * H_DIM + threadIdx.x];
        ht[threadIdx.x] = g_HT[b * H_DIM + threadIdx.x];
    }
    __syncthreads();
    for (int i = threadIdx.x; i < AV; i += 256) {
        int v = i / 101, t = i - v * 101;
        g_VT[b * AV + i] = hv[v] * ht[t];
    }
}

// ---------------- dummy kernel: positions main_kernel as the 4th launch for ncu ----------------
__global__ void dummy_kernel() {}

// ---------------- kernel 3: main split-K GEMM (fp16 m16n8k16 MMA, fp32 smem) ----------------
// 8 warps, warp grid 2M x 4N (warp tile 64 x 80). KT=32.
// SMEM per stage (fp32, unchanged layout): A[128 rows][32 words], B[320 rows][32 words],
// k contiguous, 16B chunks XOR-swizzled: chunk' = chunk ^ ((row & 1) * 4).
// k16-group g: a thread's lds128 at chunk (4g+lc) yields phys k 16g+4lc+{0..3}, used as
// mma slots {2lc, 2lc+1, 2lc+8, 2lc+9} of group g — a bijection applied identically to
// A and B, so the contraction is exact.
__global__ void __launch_bounds__(NTHR, 1) main_kernel(const float* __restrict__ W1) {
    extern __shared__ char dyn[];
    uint32_t base_s = smem_u32(dyn);

    int tid = threadIdx.x, wid = tid >> 5, lane = tid & 31;
    int cta = blockIdx.x;
    int wm = wid & 1;          // M half: rows wm*64
    int wn = wid >> 1;         // N block: cols wn*80
    int lr = lane >> 2;        // 0..7
    int lc = lane & 3;         // 0..3
    uint32_t swlo = (uint32_t)(lr & 1) * 4;   // consumer swizzle (row parity == lr parity)

    // contiguous K-tile range for this CTA
    int q = TILES / NCTA;                  // 217
    int r = TILES - q * NCTA;              // 81
    int t0 = cta * q + min(cta, r);
    int nt = q + (cta < r ? 1 : 0);

    // ---- producer state (rolling, advanced once per produced tile) ----
    int kp = t0 * KT;
    int ap = kp / AV;
    int vp = kp - ap * AV;

    int prow0 = wid * 8 + (lane >> 2);
    int pc0   = lane & 3;
    int bn0 = tid >> 5;
    int bw0 = tid & 31;
    const float* Wrow = W1 + (size_t)bn0 * F_DIM;
    uint32_t bdst0 = (uint32_t)(bn0 * 128 + (((bw0 >> 2) ^ ((bn0 & 1) * 4)) * 16) + (bw0 & 3) * 4);

    float acc[4][10][4];
    #pragma unroll
    for (int m = 0; m < 4; m++)
        #pragma unroll
        for (int n = 0; n < 10; n++)
            #pragma unroll
            for (int e = 0; e < 4; e++) acc[m][n][e] = 0.0f;

#define PRODUCE(S) do {                                                               \
    uint32_t aB = base_s + (S) * STG_BYTES;                                           \
    uint32_t bB = aB + A_BYTES;                                                       \
    /* ---- A tile (raw fp32 products; consumer cvt does the rounding) ---- */        \
    if (vp <= AV - KT && kp + KT <= F_DIM) {  /* fast: 'a' constant over tile */      \
        _Pragma("unroll")                                                             \
        for (int it = 0; it < 2; it++) {                                              \
            int row = it * 64 + prow0;                                                \
            float ha = g_HA[row * H_DIM + ap];                                        \
            const float* vrow = g_VT + (size_t)row * AV + vp;                         \
            uint32_t abase = aB + row * 128;                                          \
            uint32_t rsw = (uint32_t)(row & 1) * 4;                                   \
            _Pragma("unroll")                                                         \
            for (int j = 0; j < 2; j++) {                                             \
                int c = pc0 + 4 * j;                                                  \
                uint32_t v0 = __float_as_uint(ha * vrow[4 * c + 0]);                  \
                uint32_t v1 = __float_as_uint(ha * vrow[4 * c + 1]);                  \
                uint32_t v2 = __float_as_uint(ha * vrow[4 * c + 2]);                  \
                uint32_t v3 = __float_as_uint(ha * vrow[4 * c + 3]);                  \
                sts128(abase + (((uint32_t)c ^ rsw) * 16), v0, v1, v2, v3);           \
            }                                                                         \
        }                                                                             \
    } else {                                  /* slow: per-element, division-free */  \
        _Pragma("unroll")                                                             \
        for (int it = 0; it < 2; it++) {                                              \
            int row = it * 64 + prow0;                                                \
            uint32_t abase = aB + row * 128;                                          \
            uint32_t rsw = (uint32_t)(row & 1) * 4;                                   \
            _Pragma("unroll")                                                         \
            for (int j = 0; j < 2; j++) {                                             \
                int c = pc0 + 4 * j;                                                  \
                uint32_t v[4];                                                        \
                _Pragma("unroll")                                                     \
                for (int e = 0; e < 4; e++) {                                         \
                    int off = 4 * c + e;                                              \
                    int k = kp + off;                                                 \
                    float val = 0.0f;                                                 \
                    if (k < F_DIM) {                                                  \
                        int vv = vp + off;                                            \
                        int wrap = (vv >= AV);                                        \
                        int a = ap + wrap;                                            \
                        int vt = vv - (wrap ? AV : 0);                                \
                        val = g_HA[row * H_DIM + a] * g_VT[(size_t)row * AV + vt];    \
                    }                                                                 \
                    v[e] = __float_as_uint(val);                                      \
                }                                                                     \
                sts128(abase + (((uint32_t)c ^ rsw) * 16), v[0], v[1], v[2], v[3]);   \
            }                                                                         \
        }                                                                             \
    }                                                                                 \
    /* ---- B tile: 300 rows x 32 words, rolling pointers ---- */                     \
    {                                                                                 \
        int kk = kp + bw0;                                                            \
        const float* src = Wrow + ((kk < F_DIM) ? kk : 0);  /* clamp: A zeros cover */\
        uint32_t dst = bB + bdst0;                                                    \
        _Pragma("unroll")                                                             \
        for (int i = 0; i < 37; i++) {                                                \
            cpasync4(dst, src);                                                       \
            dst += 8 * 128;                                                           \
            src += (size_t)8 * F_DIM;                                                 \
        }                                                                             \
        if (tid < 128) cpasync4(dst, src);  /* rows 296..299 */                       \
    }                                                                                 \
    kp += KT; vp += KT; if (vp >= AV) { vp -= AV; ap++; }                             \
} while (0)

    // prologue: produce stages 0,1
    PRODUCE(0); cp_commit();
    PRODUCE(1); cp_commit();

    uint32_t aoff = (uint32_t)((wm * 64 + lr) * 128);
    uint32_t boff = (uint32_t)((wn * 80 + lr) * 128);

    int stage_c = 0, stage_p = 2;
    for (int c = 0; c < nt; c++) {
        cp_wait1();
        __syncthreads();
        if (c + 2 < nt) PRODUCE(stage_p);
        cp_commit();

        uint32_t aB = base_s + stage_c * STG_BYTES;
        uint32_t bB = aB + A_BYTES;

        #pragma unroll
        for (int g = 0; g < 2; g++) {
            uint32_t chc = (((uint32_t)(4 * g + lc)) ^ swlo) * 16;
            // A fragments for this k16 group: 8 lds128 -> 16 half2 regs
            // Af[m] = {a0,a1,a2,a3}: a0=(row lr, slots 2lc,2lc+1), a1=(row lr+8, same),
            //                        a2=(row lr, slots +8), a3=(row lr+8, slots +8)
            uint32_t Af[4][4];
            {
                uint32_t aaddr = aB + aoff + chc;
                #pragma unroll
                for (int m = 0; m < 4; m++) {
                    uint32_t ra[4], rb[4];
                    lds128(aaddr,           ra[0], ra[1], ra[2], ra[3]);
                    lds128(aaddr + 8 * 128, rb[0], rb[1], rb[2], rb[3]);
                    aaddr += 16 * 128;
                    Af[m][0] = cvt2h(__uint_as_float(ra[1]), __uint_as_float(ra[0]));
                    Af[m][1] = cvt2h(__uint_as_float(rb[1]), __uint_as_float(rb[0]));
                    Af[m][2] = cvt2h(__uint_as_float(ra[3]), __uint_as_float(ra[2]));
                    Af[m][3] = cvt2h(__uint_as_float(rb[3]), __uint_as_float(rb[2]));
                }
            }
            // B fragments stream through a 2-deep rolling buffer (prefetch n+1)
            uint32_t baddr = bB + boff + chc;
            uint32_t bcur[4], bnxt[4];
            lds128(baddr, bcur[0], bcur[1], bcur[2], bcur[3]);
            #pragma unroll
            for (int n = 0; n < 10; n++) {
                if (n < 9) {
                    baddr += 8 * 128;
                    lds128(baddr, bnxt[0], bnxt[1], bnxt[2], bnxt[3]);
                }
                uint32_t b0 = cvt2h(__uint_as_float(bcur[1]), __uint_as_float(bcur[0]));
                uint32_t b1 = cvt2h(__uint_as_float(bcur[3]), __uint_as_float(bcur[2]));
                #pragma unroll
                for (int m = 0; m < 4; m++) {
                    mma_f16(acc[m][n][0], acc[m][n][1], acc[m][n][2], acc[m][n][3],
                            Af[m][0], Af[m][1], Af[m][2], Af[m][3], b0, b1);
                }
                #pragma unroll
                for (int e = 0; e < 4; e++) bcur[e] = bnxt[e];
            }
        }
        stage_c = (stage_c == 2) ? 0 : stage_c + 1;
        stage_p = (stage_p == 2) ? 0 : stage_p + 1;
    }

    // ---- epilogue: deterministic per-CTA partials ----
    float* dst = g_part + (size_t)cta * B_DIM * P_DIM;
    #pragma unroll
    for (int m = 0; m < 4; m++) {
        int row = wm * 64 + m * 16 + lr;
        #pragma unroll
        for (int n = 0; n < 10; n++) {
            int col = wn * 80 + n * 8 + lc * 2;
            if (col < 300) {
                float2 v0 = make_float2(acc[m][n][0], acc[m][n][1]);
                float2 v1 = make_float2(acc[m][n][2], acc[m][n][3]);
                *reinterpret_cast<float2*>(dst + (size_t)row * P_DIM + col) = v0;
                *reinterpret_cast<float2*>(dst + (size_t)(row + 8) * P_DIM + col) = v1;
            }
        }
    }
#undef PRODUCE
}

// ---------------- kernel 4a: split-K reduce phase 1 (148 -> 8) ----------------
__global__ void reduce1_kernel() {
    const int NG4 = B_DIM * P_DIM / 4;                    // 9600
    int g4 = blockIdx.x * blockDim.x + threadIdx.x;
    if (g4 >= NG4) return;
    int part = blockIdx.y;                                // 0..7
    int c0 = part * 18 + min(part, 4);                    // 148 = 4*19 + 4*18
    int cn = 18 + (part < 4 ? 1 : 0);
    const float4* base = reinterpret_cast<const float4*>(g_part) + (size_t)c0 * NG4 + g4;
    float4 s0 = make_float4(0.f, 0.f, 0.f, 0.f);
    float4 s1 = make_float4(0.f, 0.f, 0.f, 0.f);
    float4 s2 = make_float4(0.f, 0.f, 0.f, 0.f);
    float4 s3 = make_float4(0.f, 0.f, 0.f, 0.f);
    int c = 0;
    #pragma unroll
    for (; c + 4 <= 18; c += 4) {
        float4 v0 = base[(size_t)(c + 0) * NG4];
        float4 v1 = base[(size_t)(c + 1) * NG4];
        float4 v2 = base[(size_t)(c + 2) * NG4];
        float4 v3 = base[(size_t)(c + 3) * NG4];
        s0.x += v0.x; s0.y += v0.y; s0.z += v0.z; s0.w += v0.w;
        s1.x += v1.x; s1.y += v1.y; s1.z += v1.z; s1.w += v1.w;
        s2.x += v2.x; s2.y += v2.y; s2.z += v2.z; s2.w += v2.w;
        s3.x += v3.x; s3.y += v3.y; s3.z += v3.z; s3.w += v3.w;
    }
    for (; c < cn; c++) {
        float4 v0 = base[(size_t)c * NG4];
        s0.x += v0.x; s0.y += v0.y; s0.z += v0.z; s0.w += v0.w;
    }
    float4 o;
    o.x = (s0.x + s1.x) + (s2.x + s3.x);
    o.y = (s0.y + s1.y) + (s2.y + s3.y);
    o.z = (s0.z + s1.z) + (s2.z + s3.z);
    o.w = (s0.w + s1.w) + (s2.w + s3.w);
    reinterpret_cast<float4*>(g_R4)[part * NG4 + g4] = o;
}

// ---------------- kernel 4b: reduce phase 2 + bias + relu ----------------
__global__ void reduce2_kernel(const float* __restrict__ b1) {
    const int NG4 = B_DIM * P_DIM / 4;
    int g4 = blockIdx.x * blockDim.x + threadIdx.x;
    if (g4 >= NG4) return;
    const float4* R = reinterpret_cast<const float4*>(g_R4);
    float sx = 0.f, sy = 0.f, sz = 0.f, sw = 0.f;
    #pragma unroll
    for (int p = 0; p < RPARTS; p++) {
        float4 v = R[p * NG4 + g4];
        sx += v.x; sy += v.y; sz += v.z; sw += v.w;
    }
    int col = (g4 * 4) % P_DIM;
    float4 o;
    o.x = fmaxf(sx + __ldg(b1 + col + 0), 0.f);
    o.y = fmaxf(sy + __ldg(b1 + col + 1), 0.f);
    o.z = fmaxf(sz + __ldg(b1 + col + 2), 0.f);
    o.w = fmaxf(sw + __ldg(b1 + col + 3), 0.f);
    reinterpret_cast<float4*>(g_H)[g4] = o;
}

// ---------------- kernel 5: output layer ----------------
__global__ void out_kernel(const float* __restrict__ W2, const float* __restrict__ b2,
                           float* __restrict__ out) {
    __shared__ float w[P_DIM];
    int o = blockIdx.x;
    for (int i = threadIdx.x; i < P_DIM; i += blockDim.x) w[i] = W2[o * P_DIM + i];
    __syncthreads();
    int b = threadIdx.x;
    if (b < B_DIM) {
        const float* h = g_H + b * P_DIM;
        float s = __ldg(b2 + o);
        #pragma unroll 4
        for (int p = 0; p < P_DIM; p++) s += h[p] * w[p];
        out[b * P_DIM + o] = fmaxf(s, 0.0f);
    }
}

// ---------------- launch ----------------
extern "C" void kernel_launch(void* const* d_in, const int* in_sizes, int n_in,
                              void* d_out, int out_size) {
    const float* ax = (const float*)d_in[0];
    const float* vx = (const float*)d_in[1];
    const float* tx = (const float*)d_in[2];
    const float* Wa = (const float*)d_in[3];
    const float* ba = (const float*)d_in[4];
    const float* Wv = (const float*)d_in[5];
    const float* bv = (const float*)d_in[6];
    const float* Wt = (const float*)d_in[7];
    const float* bt = (const float*)d_in[8];
    const float* W1 = (const float*)d_in[9];
    const float* b1 = (const float*)d_in[10];
    const float* W2 = (const float*)d_in[11];
    const float* b2 = (const float*)d_in[12];
    float* out = (float*)d_out;

    cudaFuncSetAttribute(main_kernel, cudaFuncAttributeMaxDynamicSharedMemorySize, DYN_SMEM);

    enc_kernel<<<dim3(B_DIM, 3), 128>>>(ax, vx, tx, Wa, ba, Wv, bv, Wt, bt);
    vt_kernel<<<B_DIM, 256>>>();
    dummy_kernel<<<1, 32>>>();   // positions main_kernel as launch #4 for the ncu window
    main_kernel<<<NCTA, NTHR, DYN_SMEM>>>(W1);
    reduce1_kernel<<<dim3((B_DIM * P_DIM / 4 + 255) / 256, RPARTS), 256>>>();
    reduce2_kernel<<<(B_DIM * P_DIM / 4 + 255) / 256, 256>>>(b1);
    out_kernel<<<P_DIM, 128>>>(W2, b2, out);
}